// round 12
// baseline (speedup 1.0000x reference)
#include <cuda_runtime.h>
#include <cuda_bf16.h>
#include <mma.h>
#include <cstdint>
using namespace nvcuda;

#define N_NODES   50000
#define EMB       320
#define HID       64
#define NH        128
#define N_EDGES   400000
#define NTILES    391          // ceil(50000/128)
#define KC        32
#define NCHUNK    (EMB / KC)   // 10
#define BKF       16
#define NCHUNKF   (EMB / BKF)  // 20

#define AP 40    // wmma A smem pitch (bf16)
#define BP 136   // wmma B smem pitch (bf16)

// Scratch (no allocations allowed)
__device__ __align__(16) float g_P[N_NODES * NH];
__device__ __align__(16) float g_w[N_EDGES];
__device__ __align__(16) float g_cvec[HID];
__device__ __align__(16) __nv_bfloat16 g_W1h[640 * 64];
__device__ __align__(16) __nv_bfloat16 g_W1l[640 * 64];
__device__ int g_idx64;

// ---------------------------------------------------------------------------
// Kernel 0: detect edge_index element width (int32 vs int64, little-endian).
// ---------------------------------------------------------------------------
__global__ void detect_kernel(const int* __restrict__ ei_raw) {
    int is64 = 1;
    #pragma unroll
    for (int i = 0; i < 32; i++)
        if (ei_raw[2 * i + 1] != 0) { is64 = 0; break; }
    g_idx64 = is64;
}

// ---------------------------------------------------------------------------
// Kernel S: W1[0:640] fp32 -> (hi, lo) bf16 split (tiny, one-shot).
// ---------------------------------------------------------------------------
__global__ __launch_bounds__(256) void splitW1_kernel(const float* __restrict__ W1) {
    int i = blockIdx.x * blockDim.x + threadIdx.x;
    if (i >= 640 * 64 / 4) return;
    float4 v = *reinterpret_cast<const float4*>(&W1[i * 4]);
    float a[4] = {v.x, v.y, v.z, v.w};
    __nv_bfloat16 h[4], l[4];
    #pragma unroll
    for (int q = 0; q < 4; q++) {
        h[q] = __float2bfloat16(a[q]);
        l[q] = __float2bfloat16(a[q] - __bfloat162float(h[q]));
    }
    *reinterpret_cast<uint2*>(&g_W1h[i * 4]) = *reinterpret_cast<uint2*>(h);
    *reinterpret_cast<uint2*>(&g_W1l[i * 4]) = *reinterpret_cast<uint2*>(l);
}

// ---------------------------------------------------------------------------
// Kernel 1: HYBRID GEMM.  bid%3 != 2 -> wmma bf16 3-term (tensor pipe);
//                         bid%3 == 2 -> fp32 FFMA (fma pipe).
// Both paths verified standalone (71.6us / 137us); co-residency adds rates.
// ---------------------------------------------------------------------------
struct WmmaSmem {
    __nv_bfloat16 Ah[128][AP], Al[128][AP];
    __nv_bfloat16 Bh[KC][BP],  Bl[KC][BP];
};
struct FfmaSmem {
    float As[BKF][128];
    float Bs[BKF][128];
};

__global__ __launch_bounds__(256, 2) void gemm_hybrid(const float* __restrict__ embed,
                                                      const float* __restrict__ W1) {
    __shared__ __align__(16) char smem_u[sizeof(WmmaSmem)];

    const int tid  = threadIdx.x;
    const int wid  = tid >> 5;
    const int lane = tid & 31;
    const int m0   = blockIdx.x * 128;

    if ((blockIdx.x % 3) != 2) {
        // ===================== wmma bf16 3-term path =====================
        WmmaSmem& S = *reinterpret_cast<WmmaSmem*>(smem_u);
        const int warp_m = wid & 1;
        const int warp_n = wid >> 1;

        const int ar  = tid >> 1;
        const int aks = (tid & 1) * 16;
        const int a_gm = m0 + ar;
        const int bu4  = tid & 7;
        const int bhalf = (tid >> 3) & 1;
        const int bkr   = tid >> 4;

        wmma::fragment<wmma::accumulator, 16, 16, 16, float> acc[4][2];
        #pragma unroll
        for (int i = 0; i < 4; i++)
            #pragma unroll
            for (int j = 0; j < 2; j++)
                wmma::fill_fragment(acc[i][j], 0.f);

        float4 rA[4];
        uint4  rBh[2], rBl[2];

        auto loadA = [&](int k0) {
            if (a_gm < N_NODES) {
                const float* p = &embed[(size_t)a_gm * EMB + k0 + aks];
                #pragma unroll
                for (int q = 0; q < 4; q++)
                    rA[q] = *reinterpret_cast<const float4*>(p + q * 4);
            } else {
                #pragma unroll
                for (int q = 0; q < 4; q++)
                    rA[q] = make_float4(0.f, 0.f, 0.f, 0.f);
            }
        };
        auto loadB = [&](int k0) {
            #pragma unroll
            for (int p = 0; p < 2; p++) {
                size_t off = (size_t)(bhalf * 320 + k0 + bkr + p * 16) * 64 + bu4 * 8;
                rBh[p] = *reinterpret_cast<const uint4*>(&g_W1h[off]);
                rBl[p] = *reinterpret_cast<const uint4*>(&g_W1l[off]);
            }
        };
        auto stsA = [&]() {
            #pragma unroll
            for (int q = 0; q < 4; q++) {
                float a[4] = {rA[q].x, rA[q].y, rA[q].z, rA[q].w};
                __nv_bfloat16 h[4], l[4];
                #pragma unroll
                for (int i = 0; i < 4; i++) {
                    h[i] = __float2bfloat16(a[i]);
                    l[i] = __float2bfloat16(a[i] - __bfloat162float(h[i]));
                }
                *reinterpret_cast<uint2*>(&S.Ah[ar][aks + q * 4]) = *reinterpret_cast<uint2*>(h);
                *reinterpret_cast<uint2*>(&S.Al[ar][aks + q * 4]) = *reinterpret_cast<uint2*>(l);
            }
        };
        auto stsB = [&]() {
            #pragma unroll
            for (int p = 0; p < 2; p++) {
                *reinterpret_cast<uint4*>(&S.Bh[bkr + p * 16][bhalf * 64 + bu4 * 8]) = rBh[p];
                *reinterpret_cast<uint4*>(&S.Bl[bkr + p * 16][bhalf * 64 + bu4 * 8]) = rBl[p];
            }
        };

        loadA(0);
        loadB(0);
        stsA();
        stsB();
        __syncthreads();

        for (int c = 0; c < NCHUNK; c++) {
            if (c + 1 < NCHUNK) {
                loadA((c + 1) * KC);
                loadB((c + 1) * KC);
            }

            #pragma unroll
            for (int ks = 0; ks < 2; ks++) {
                wmma::fragment<wmma::matrix_b, 16, 16, 16, __nv_bfloat16, wmma::row_major> bh[2], bl[2];
                #pragma unroll
                for (int j = 0; j < 2; j++) {
                    wmma::load_matrix_sync(bh[j], &S.Bh[ks * 16][warp_n * 32 + j * 16], BP);
                    wmma::load_matrix_sync(bl[j], &S.Bl[ks * 16][warp_n * 32 + j * 16], BP);
                }
                #pragma unroll
                for (int i = 0; i < 4; i++) {
                    wmma::fragment<wmma::matrix_a, 16, 16, 16, __nv_bfloat16, wmma::row_major> fah, fal;
                    wmma::load_matrix_sync(fah, &S.Ah[warp_m * 64 + i * 16][ks * 16], AP);
                    wmma::load_matrix_sync(fal, &S.Al[warp_m * 64 + i * 16][ks * 16], AP);
                    #pragma unroll
                    for (int j = 0; j < 2; j++) {
                        wmma::mma_sync(acc[i][j], fah, bh[j], acc[i][j]);
                        wmma::mma_sync(acc[i][j], fah, bl[j], acc[i][j]);
                        wmma::mma_sync(acc[i][j], fal, bh[j], acc[i][j]);
                    }
                }
            }
            __syncthreads();
            if (c + 1 < NCHUNK) {
                stsA();
                stsB();
                __syncthreads();
            }
        }

        #pragma unroll
        for (int i = 0; i < 4; i++) {
            int gm = m0 + warp_m * 64 + i * 16;
            if (gm < N_NODES) {
                #pragma unroll
                for (int j = 0; j < 2; j++)
                    wmma::store_matrix_sync(&g_P[(size_t)gm * NH + warp_n * 32 + j * 16],
                                            acc[i][j], NH, wmma::mem_row_major);
            }
        }
    } else {
        // ===================== fp32 FFMA path =====================
        FfmaSmem& S = *reinterpret_cast<FfmaSmem*>(smem_u);
        const int wm = wid & 3;
        const int wn = wid >> 2;
        const int tm = lane & 3;
        const int tn = lane >> 2;

        const int am = tid >> 1;
        const int ak = (tid & 1) * 8;
        const int a_gm = m0 + am;
        const int bn4 = tid & 31;
        const int bkl = tid >> 5;
        const int bhalf = bn4 >> 4;
        const int bcol  = (bn4 & 15) * 4;
        const long long brow_base = (long long)bhalf * 320;

        float4 rA0, rA1, rB0, rB1;
        float acc[8][8];
        #pragma unroll
        for (int i = 0; i < 8; i++)
            #pragma unroll
            for (int j = 0; j < 8; j++) acc[i][j] = 0.f;

        auto loadA = [&](int k0, float4& r0, float4& r1) {
            if (a_gm < N_NODES) {
                const float* p = &embed[(size_t)a_gm * EMB + k0 + ak];
                r0 = *reinterpret_cast<const float4*>(p);
                r1 = *reinterpret_cast<const float4*>(p + 4);
            } else {
                r0 = make_float4(0.f, 0.f, 0.f, 0.f);
                r1 = r0;
            }
        };
        auto loadB = [&](int k0, float4& r0, float4& r1) {
            r0 = *reinterpret_cast<const float4*>(&W1[(brow_base + k0 + bkl) * 64 + bcol]);
            r1 = *reinterpret_cast<const float4*>(&W1[(brow_base + k0 + bkl + 8) * 64 + bcol]);
        };
        auto stsA = [&](const float4& r0, const float4& r1) {
            S.As[ak + 0][am] = r0.x; S.As[ak + 1][am] = r0.y;
            S.As[ak + 2][am] = r0.z; S.As[ak + 3][am] = r0.w;
            S.As[ak + 4][am] = r1.x; S.As[ak + 5][am] = r1.y;
            S.As[ak + 6][am] = r1.z; S.As[ak + 7][am] = r1.w;
        };
        auto stsB = [&](const float4& r0, const float4& r1) {
            *reinterpret_cast<float4*>(&S.Bs[bkl][bn4 * 4])     = r0;
            *reinterpret_cast<float4*>(&S.Bs[bkl + 8][bn4 * 4]) = r1;
        };

        loadA(0, rA0, rA1);
        loadB(0, rB0, rB1);
        stsA(rA0, rA1);
        stsB(rB0, rB1);
        __syncthreads();

        for (int c = 0; c < NCHUNKF; c++) {
            if (c + 1 < NCHUNKF) {
                loadA((c + 1) * BKF, rA0, rA1);
                loadB((c + 1) * BKF, rB0, rB1);
            }
            #pragma unroll
            for (int k = 0; k < BKF; k++) {
                float4 a0 = *reinterpret_cast<const float4*>(&S.As[k][wm * 32 + tm * 4]);
                float4 a1 = *reinterpret_cast<const float4*>(&S.As[k][wm * 32 + tm * 4 + 16]);
                float4 b0 = *reinterpret_cast<const float4*>(&S.Bs[k][wn * 64 + tn * 4]);
                float4 b1 = *reinterpret_cast<const float4*>(&S.Bs[k][wn * 64 + tn * 4 + 32]);
                float av[8] = {a0.x, a0.y, a0.z, a0.w, a1.x, a1.y, a1.z, a1.w};
                float bv[8] = {b0.x, b0.y, b0.z, b0.w, b1.x, b1.y, b1.z, b1.w};
                #pragma unroll
                for (int i = 0; i < 8; i++)
                    #pragma unroll
                    for (int j = 0; j < 8; j++)
                        acc[i][j] = fmaf(av[i], bv[j], acc[i][j]);
            }
            __syncthreads();
            if (c + 1 < NCHUNKF) {
                stsA(rA0, rA1);
                stsB(rB0, rB1);
                __syncthreads();
            }
        }

        #pragma unroll
        for (int i = 0; i < 8; i++) {
            int gm = m0 + wm * 32 + tm * 4 + (i & 3) + (i >> 2) * 16;
            if (gm < N_NODES) {
                float* dst = &g_P[(size_t)gm * NH + wn * 64 + tn * 4];
                *reinterpret_cast<float4*>(dst)      = make_float4(acc[i][0], acc[i][1], acc[i][2], acc[i][3]);
                *reinterpret_cast<float4*>(dst + 32) = make_float4(acc[i][4], acc[i][5], acc[i][6], acc[i][7]);
            }
        }
    }
}

// ---------------------------------------------------------------------------
// Kernel 2: cvec — k-parallel (512 thr, 8 segments x 40 k, smem reduce).
// ---------------------------------------------------------------------------
__global__ __launch_bounds__(512) void cvec_kernel(const float* __restrict__ embed,
                                                   const float* __restrict__ W1,
                                                   const float* __restrict__ b1,
                                                   const int*   __restrict__ nid) {
    __shared__ float red[8][64];
    const int j = threadIdx.x & 63;
    const int s = threadIdx.x >> 6;
    const int n = nid[0];
    const float* er = &embed[(size_t)n * EMB];

    float sum = 0.f;
    #pragma unroll
    for (int q = 0; q < 40; q++) {
        int k = s * 40 + q;
        sum = fmaf(er[k], W1[(640 + k) * 64 + j], sum);
    }
    red[s][j] = sum;
    __syncthreads();
    if (s < 4) red[s][j] += red[s + 4][j];
    __syncthreads();
    if (s < 2) red[s][j] += red[s + 2][j];
    __syncthreads();
    if (s == 0) g_cvec[j] = red[0][j] + red[1][j] + b1[j];
}

// ---------------------------------------------------------------------------
// Kernel 3a: gather + dot (no transcendentals). 8 lanes/edge, 4 edges/warp.
// ---------------------------------------------------------------------------
__global__ __launch_bounds__(256) void edge_dot_kernel(const void* __restrict__ ei_raw,
                                                       const float* __restrict__ W2) {
    const int lane = threadIdx.x & 31;
    const int sub  = lane >> 3;
    const int j8   = lane & 7;
    const int warpGlobal = (blockIdx.x * blockDim.x + threadIdx.x) >> 5;
    const int nWarps = (gridDim.x * blockDim.x) >> 5;

    const float4 cv0 = *reinterpret_cast<const float4*>(&g_cvec[j8 * 8]);
    const float4 cv1 = *reinterpret_cast<const float4*>(&g_cvec[j8 * 8 + 4]);
    const float4 w20 = *reinterpret_cast<const float4*>(&W2[j8 * 8]);
    const float4 w21 = *reinterpret_cast<const float4*>(&W2[j8 * 8 + 4]);
    const int is64 = g_idx64;
    const long long* e64 = (const long long*)ei_raw;
    const int*       e32 = (const int*)ei_raw;

    for (int e = warpGlobal * 4 + sub; e < N_EDGES; e += nWarps * 4) {
        int col, row;
        if (is64) { col = (int)e64[e]; row = (int)e64[N_EDGES + e]; }
        else      { col = e32[e];      row = e32[N_EDGES + e]; }

        const float* Pc = &g_P[(size_t)col * NH + j8 * 8];
        const float* Pr = &g_P[(size_t)row * NH + 64 + j8 * 8];
        float4 a0 = *reinterpret_cast<const float4*>(Pc);
        float4 a1 = *reinterpret_cast<const float4*>(Pc + 4);
        float4 b0 = *reinterpret_cast<const float4*>(Pr);
        float4 b1 = *reinterpret_cast<const float4*>(Pr + 4);

        float p;
        p  = fmaxf(a0.x + b0.x + cv0.x, 0.f) * w20.x;
        p  = fmaf(fmaxf(a0.y + b0.y + cv0.y, 0.f), w20.y, p);
        p  = fmaf(fmaxf(a0.z + b0.z + cv0.z, 0.f), w20.z, p);
        p  = fmaf(fmaxf(a0.w + b0.w + cv0.w, 0.f), w20.w, p);
        p  = fmaf(fmaxf(a1.x + b1.x + cv1.x, 0.f), w21.x, p);
        p  = fmaf(fmaxf(a1.y + b1.y + cv1.y, 0.f), w21.y, p);
        p  = fmaf(fmaxf(a1.z + b1.z + cv1.z, 0.f), w21.z, p);
        p  = fmaf(fmaxf(a1.w + b1.w + cv1.w, 0.f), w21.w, p);

        p += __shfl_xor_sync(0xffffffffu, p, 4);
        p += __shfl_xor_sync(0xffffffffu, p, 2);
        p += __shfl_xor_sync(0xffffffffu, p, 1);

        if (j8 == 0) g_w[e] = p;
    }
}

// ---------------------------------------------------------------------------
// Kernel 3b: dense gate pass (tmp==1 fast path: no logs).
// ---------------------------------------------------------------------------
__global__ __launch_bounds__(256) void gate_kernel(const float* __restrict__ eps,
                                                   const float* __restrict__ tmp,
                                                   const float* __restrict__ b2,
                                                   float* __restrict__ out) {
    int i = blockIdx.x * blockDim.x + threadIdx.x;
    if (i * 4 >= N_EDGES) return;
    const float bias = 0.0001f, c1 = 1.f - 2.f * 0.0001f;
    float4 ev = *reinterpret_cast<const float4*>(&eps[i * 4]);
    float4 wv = *reinterpret_cast<const float4*>(&g_w[i * 4]);
    float t = tmp[0];
    float bb = b2[0];
    float e[4] = {fmaf(ev.x, c1, bias), fmaf(ev.y, c1, bias),
                  fmaf(ev.z, c1, bias), fmaf(ev.w, c1, bias)};
    float w[4] = {wv.x + bb, wv.y + bb, wv.z + bb, wv.w + bb};
    float o[4];
    if (t == 1.0f) {
        #pragma unroll
        for (int q = 0; q < 4; q++) {
            float s = __expf(-w[q]);
            o[q] = __fdividef(e[q], fmaf(s, 1.f - e[q], e[q]));
        }
    } else {
        float inv_t = __fdividef(1.f, t);
        #pragma unroll
        for (int q = 0; q < 4; q++) {
            float gate = (__logf(e[q]) - __logf(1.f - e[q]) + w[q]) * inv_t;
            o[q] = __fdividef(1.f, 1.f + __expf(-gate));
        }
    }
    *reinterpret_cast<float4*>(&out[i * 4]) = make_float4(o[0], o[1], o[2], o[3]);
}

// ---------------------------------------------------------------------------
// Inputs: 0:x 1:embed 2:edge_index 3:node_id 4:tmp 5:eps 6:W1 7:b1 8:W2 9:b2
// ---------------------------------------------------------------------------
extern "C" void kernel_launch(void* const* d_in, const int* in_sizes, int n_in,
                              void* d_out, int out_size) {
    const float* embed = (const float*)d_in[1];
    const void*  ei    = d_in[2];
    const int*   nid   = (const int*)d_in[3];
    const float* tmp   = (const float*)d_in[4];
    const float* eps   = (const float*)d_in[5];
    const float* W1    = (const float*)d_in[6];
    const float* b1    = (const float*)d_in[7];
    const float* W2    = (const float*)d_in[8];
    const float* b2    = (const float*)d_in[9];
    float* out = (float*)d_out;

    detect_kernel<<<1, 1>>>((const int*)ei);
    splitW1_kernel<<<(640 * 64 / 4 + 255) / 256, 256>>>(W1);
    cvec_kernel<<<1, 512>>>(embed, W1, b1, nid);
    gemm_hybrid<<<NTILES, 256>>>(embed, W1);
    edge_dot_kernel<<<1184, 256>>>(ei, W2);
    gate_kernel<<<(N_EDGES / 4 + 255) / 256, 256>>>(eps, tmp, b2, out);
}

// round 13
// speedup vs baseline: 1.4957x; 1.4957x over previous
#include <cuda_runtime.h>
#include <cuda_bf16.h>
#include <mma.h>
#include <cstdint>
using namespace nvcuda;

#define N_NODES   50000
#define EMB       320
#define HID       64
#define NH        128
#define N_EDGES   400000
#define NTILES    391          // ceil(50000/128)
#define KC        32
#define NCHUNK    (EMB / KC)   // 10

#define AP 40    // A smem pitch (bf16)
#define BP 136   // B smem pitch (bf16)

// dynamic smem layout (bytes)
#define SZ_A   (128 * AP * 2)          // 10240 per (stage, hi/lo)
#define SZ_B   (KC * BP * 2)           // 8704  per (stage, hi/lo)
#define SMEM_TOTAL (2 * (2 * SZ_A + 2 * SZ_B))   // 75776

// Scratch (no allocations allowed)
__device__ __align__(16) float g_P[N_NODES * NH];
__device__ __align__(16) float g_w[N_EDGES];
__device__ __align__(16) float g_cvec[HID];
__device__ __align__(16) __nv_bfloat16 g_W1h[640 * 64];
__device__ __align__(16) __nv_bfloat16 g_W1l[640 * 64];
__device__ int g_idx64;

// ---------------------------------------------------------------------------
// Kernel 0: detect edge_index element width (int32 vs int64, little-endian).
// ---------------------------------------------------------------------------
__global__ void detect_kernel(const int* __restrict__ ei_raw) {
    int is64 = 1;
    #pragma unroll
    for (int i = 0; i < 32; i++)
        if (ei_raw[2 * i + 1] != 0) { is64 = 0; break; }
    g_idx64 = is64;
}

// ---------------------------------------------------------------------------
// Kernel S: W1[0:640] fp32 -> (hi, lo) bf16 split (tiny, one-shot).
// ---------------------------------------------------------------------------
__global__ __launch_bounds__(256) void splitW1_kernel(const float* __restrict__ W1) {
    int i = blockIdx.x * blockDim.x + threadIdx.x;
    if (i >= 640 * 64 / 4) return;
    float4 v = *reinterpret_cast<const float4*>(&W1[i * 4]);
    float a[4] = {v.x, v.y, v.z, v.w};
    __nv_bfloat16 h[4], l[4];
    #pragma unroll
    for (int q = 0; q < 4; q++) {
        h[q] = __float2bfloat16(a[q]);
        l[q] = __float2bfloat16(a[q] - __bfloat162float(h[q]));
    }
    *reinterpret_cast<uint2*>(&g_W1h[i * 4]) = *reinterpret_cast<uint2*>(h);
    *reinterpret_cast<uint2*>(&g_W1l[i * 4]) = *reinterpret_cast<uint2*>(l);
}

// ---------------------------------------------------------------------------
// Kernel 1: wmma bf16 3-term GEMM, 2-stage smem double buffer (1 sync/chunk).
//   P[v,0:64]  = embed[v] @ W1[0:320,:]
//   P[v,64:128]= embed[v] @ W1[320:640,:]
// Per chunk c: STS(c+1 from regs) -> LDG(c+2 into regs) -> wmma(c) -> sync.
// acc += Ah*Bh + Ah*Bl + Al*Bh  (missing Al*Bl ~ 2^-16 rel).
// ---------------------------------------------------------------------------
__global__ __launch_bounds__(256, 2) void gemm_kernel(const float* __restrict__ embed) {
    extern __shared__ __align__(16) char sm[];
    // stage s: [Ah | Al | Bh | Bl]
    auto AhP = [&](int s) { return reinterpret_cast<__nv_bfloat16*>(sm + s * (2 * SZ_A + 2 * SZ_B)); };
    auto AlP = [&](int s) { return reinterpret_cast<__nv_bfloat16*>(sm + s * (2 * SZ_A + 2 * SZ_B) + SZ_A); };
    auto BhP = [&](int s) { return reinterpret_cast<__nv_bfloat16*>(sm + s * (2 * SZ_A + 2 * SZ_B) + 2 * SZ_A); };
    auto BlP = [&](int s) { return reinterpret_cast<__nv_bfloat16*>(sm + s * (2 * SZ_A + 2 * SZ_B) + 2 * SZ_A + SZ_B); };

    const int tid = threadIdx.x;
    const int wid = tid >> 5;
    const int warp_m = wid & 1;
    const int warp_n = wid >> 1;
    const int m0 = blockIdx.x * 128;

    const int ar  = tid >> 1;
    const int aks = (tid & 1) * 16;
    const int a_gm = m0 + ar;
    const int bu4  = tid & 7;
    const int bhalf = (tid >> 3) & 1;
    const int bkr   = tid >> 4;

    wmma::fragment<wmma::accumulator, 16, 16, 16, float> acc[4][2];
    #pragma unroll
    for (int i = 0; i < 4; i++)
        #pragma unroll
        for (int j = 0; j < 2; j++)
            wmma::fill_fragment(acc[i][j], 0.f);

    float4 rA[4];
    uint4  rBh[2], rBl[2];

    auto loadA = [&](int k0) {
        if (a_gm < N_NODES) {
            const float* p = &embed[(size_t)a_gm * EMB + k0 + aks];
            #pragma unroll
            for (int q = 0; q < 4; q++)
                rA[q] = *reinterpret_cast<const float4*>(p + q * 4);
        } else {
            #pragma unroll
            for (int q = 0; q < 4; q++)
                rA[q] = make_float4(0.f, 0.f, 0.f, 0.f);
        }
    };
    auto loadB = [&](int k0) {
        #pragma unroll
        for (int p = 0; p < 2; p++) {
            size_t off = (size_t)(bhalf * 320 + k0 + bkr + p * 16) * 64 + bu4 * 8;
            rBh[p] = *reinterpret_cast<const uint4*>(&g_W1h[off]);
            rBl[p] = *reinterpret_cast<const uint4*>(&g_W1l[off]);
        }
    };
    auto sts = [&](int s) {
        __nv_bfloat16* ah = AhP(s); __nv_bfloat16* al = AlP(s);
        #pragma unroll
        for (int q = 0; q < 4; q++) {
            float a[4] = {rA[q].x, rA[q].y, rA[q].z, rA[q].w};
            __nv_bfloat16 h[4], l[4];
            #pragma unroll
            for (int i = 0; i < 4; i++) {
                h[i] = __float2bfloat16(a[i]);
                l[i] = __float2bfloat16(a[i] - __bfloat162float(h[i]));
            }
            *reinterpret_cast<uint2*>(&ah[ar * AP + aks + q * 4]) = *reinterpret_cast<uint2*>(h);
            *reinterpret_cast<uint2*>(&al[ar * AP + aks + q * 4]) = *reinterpret_cast<uint2*>(l);
        }
        __nv_bfloat16* bh = BhP(s); __nv_bfloat16* bl = BlP(s);
        #pragma unroll
        for (int p = 0; p < 2; p++) {
            *reinterpret_cast<uint4*>(&bh[(bkr + p * 16) * BP + bhalf * 64 + bu4 * 8]) = rBh[p];
            *reinterpret_cast<uint4*>(&bl[(bkr + p * 16) * BP + bhalf * 64 + bu4 * 8]) = rBl[p];
        }
    };
    auto compute = [&](int s) {
        const __nv_bfloat16* ah = AhP(s); const __nv_bfloat16* al = AlP(s);
        const __nv_bfloat16* bh = BhP(s); const __nv_bfloat16* bl = BlP(s);
        #pragma unroll
        for (int ks = 0; ks < 2; ks++) {
            wmma::fragment<wmma::matrix_b, 16, 16, 16, __nv_bfloat16, wmma::row_major> fbh[2], fbl[2];
            #pragma unroll
            for (int j = 0; j < 2; j++) {
                wmma::load_matrix_sync(fbh[j], &bh[(ks * 16) * BP + warp_n * 32 + j * 16], BP);
                wmma::load_matrix_sync(fbl[j], &bl[(ks * 16) * BP + warp_n * 32 + j * 16], BP);
            }
            #pragma unroll
            for (int i = 0; i < 4; i++) {
                wmma::fragment<wmma::matrix_a, 16, 16, 16, __nv_bfloat16, wmma::row_major> fah, fal;
                wmma::load_matrix_sync(fah, &ah[(warp_m * 64 + i * 16) * AP + ks * 16], AP);
                wmma::load_matrix_sync(fal, &al[(warp_m * 64 + i * 16) * AP + ks * 16], AP);
                #pragma unroll
                for (int j = 0; j < 2; j++) {
                    wmma::mma_sync(acc[i][j], fah, fbh[j], acc[i][j]);
                    wmma::mma_sync(acc[i][j], fah, fbl[j], acc[i][j]);
                    wmma::mma_sync(acc[i][j], fal, fbh[j], acc[i][j]);
                }
            }
        }
    };

    // prologue: chunk 0 -> stage 0; prefetch chunk 1 into regs
    loadA(0); loadB(0);
    sts(0);
    __syncthreads();
    loadA(KC); loadB(KC);

    for (int c = 0; c < NCHUNK; c++) {
        // regs currently hold chunk c+1 (when it exists): store into stage (c+1)&1
        if (c + 1 < NCHUNK) sts((c + 1) & 1);
        // prefetch chunk c+2
        if (c + 2 < NCHUNK) { loadA((c + 2) * KC); loadB((c + 2) * KC); }
        compute(c & 1);
        __syncthreads();
    }

    #pragma unroll
    for (int i = 0; i < 4; i++) {
        int gm = m0 + warp_m * 64 + i * 16;
        if (gm < N_NODES) {
            #pragma unroll
            for (int j = 0; j < 2; j++)
                wmma::store_matrix_sync(&g_P[(size_t)gm * NH + warp_n * 32 + j * 16],
                                        acc[i][j], NH, wmma::mem_row_major);
        }
    }
}

// ---------------------------------------------------------------------------
// Kernel 2: cvec — k-parallel (512 thr, 8 segments x 40 k, smem reduce).
// ---------------------------------------------------------------------------
__global__ __launch_bounds__(512) void cvec_kernel(const float* __restrict__ embed,
                                                   const float* __restrict__ W1,
                                                   const float* __restrict__ b1,
                                                   const int*   __restrict__ nid) {
    __shared__ float red[8][64];
    const int j = threadIdx.x & 63;
    const int s = threadIdx.x >> 6;
    const int n = nid[0];
    const float* er = &embed[(size_t)n * EMB];

    float sum = 0.f;
    #pragma unroll
    for (int q = 0; q < 40; q++) {
        int k = s * 40 + q;
        sum = fmaf(er[k], W1[(640 + k) * 64 + j], sum);
    }
    red[s][j] = sum;
    __syncthreads();
    if (s < 4) red[s][j] += red[s + 4][j];
    __syncthreads();
    if (s < 2) red[s][j] += red[s + 2][j];
    __syncthreads();
    if (s == 0) g_cvec[j] = red[0][j] + red[1][j] + b1[j];
}

// ---------------------------------------------------------------------------
// Kernel 3a: gather + dot (no transcendentals). 8 lanes/edge, 4 edges/warp.
// ---------------------------------------------------------------------------
__global__ __launch_bounds__(256) void edge_dot_kernel(const void* __restrict__ ei_raw,
                                                       const float* __restrict__ W2) {
    const int lane = threadIdx.x & 31;
    const int sub  = lane >> 3;
    const int j8   = lane & 7;
    const int warpGlobal = (blockIdx.x * blockDim.x + threadIdx.x) >> 5;
    const int nWarps = (gridDim.x * blockDim.x) >> 5;

    const float4 cv0 = *reinterpret_cast<const float4*>(&g_cvec[j8 * 8]);
    const float4 cv1 = *reinterpret_cast<const float4*>(&g_cvec[j8 * 8 + 4]);
    const float4 w20 = *reinterpret_cast<const float4*>(&W2[j8 * 8]);
    const float4 w21 = *reinterpret_cast<const float4*>(&W2[j8 * 8 + 4]);
    const int is64 = g_idx64;
    const long long* e64 = (const long long*)ei_raw;
    const int*       e32 = (const int*)ei_raw;

    for (int e = warpGlobal * 4 + sub; e < N_EDGES; e += nWarps * 4) {
        int col, row;
        if (is64) { col = (int)e64[e]; row = (int)e64[N_EDGES + e]; }
        else      { col = e32[e];      row = e32[N_EDGES + e]; }

        const float* Pc = &g_P[(size_t)col * NH + j8 * 8];
        const float* Pr = &g_P[(size_t)row * NH + 64 + j8 * 8];
        float4 a0 = *reinterpret_cast<const float4*>(Pc);
        float4 a1 = *reinterpret_cast<const float4*>(Pc + 4);
        float4 b0 = *reinterpret_cast<const float4*>(Pr);
        float4 b1 = *reinterpret_cast<const float4*>(Pr + 4);

        float p;
        p  = fmaxf(a0.x + b0.x + cv0.x, 0.f) * w20.x;
        p  = fmaf(fmaxf(a0.y + b0.y + cv0.y, 0.f), w20.y, p);
        p  = fmaf(fmaxf(a0.z + b0.z + cv0.z, 0.f), w20.z, p);
        p  = fmaf(fmaxf(a0.w + b0.w + cv0.w, 0.f), w20.w, p);
        p  = fmaf(fmaxf(a1.x + b1.x + cv1.x, 0.f), w21.x, p);
        p  = fmaf(fmaxf(a1.y + b1.y + cv1.y, 0.f), w21.y, p);
        p  = fmaf(fmaxf(a1.z + b1.z + cv1.z, 0.f), w21.z, p);
        p  = fmaf(fmaxf(a1.w + b1.w + cv1.w, 0.f), w21.w, p);

        p += __shfl_xor_sync(0xffffffffu, p, 4);
        p += __shfl_xor_sync(0xffffffffu, p, 2);
        p += __shfl_xor_sync(0xffffffffu, p, 1);

        if (j8 == 0) g_w[e] = p;
    }
}

// ---------------------------------------------------------------------------
// Kernel 3b: dense gate pass (tmp==1 fast path: no logs).
// ---------------------------------------------------------------------------
__global__ __launch_bounds__(256) void gate_kernel(const float* __restrict__ eps,
                                                   const float* __restrict__ tmp,
                                                   const float* __restrict__ b2,
                                                   float* __restrict__ out) {
    int i = blockIdx.x * blockDim.x + threadIdx.x;
    if (i * 4 >= N_EDGES) return;
    const float bias = 0.0001f, c1 = 1.f - 2.f * 0.0001f;
    float4 ev = *reinterpret_cast<const float4*>(&eps[i * 4]);
    float4 wv = *reinterpret_cast<const float4*>(&g_w[i * 4]);
    float t = tmp[0];
    float bb = b2[0];
    float e[4] = {fmaf(ev.x, c1, bias), fmaf(ev.y, c1, bias),
                  fmaf(ev.z, c1, bias), fmaf(ev.w, c1, bias)};
    float w[4] = {wv.x + bb, wv.y + bb, wv.z + bb, wv.w + bb};
    float o[4];
    if (t == 1.0f) {
        #pragma unroll
        for (int q = 0; q < 4; q++) {
            float s = __expf(-w[q]);
            o[q] = __fdividef(e[q], fmaf(s, 1.f - e[q], e[q]));
        }
    } else {
        float inv_t = __fdividef(1.f, t);
        #pragma unroll
        for (int q = 0; q < 4; q++) {
            float gate = (__logf(e[q]) - __logf(1.f - e[q]) + w[q]) * inv_t;
            o[q] = __fdividef(1.f, 1.f + __expf(-gate));
        }
    }
    *reinterpret_cast<float4*>(&out[i * 4]) = make_float4(o[0], o[1], o[2], o[3]);
}

// ---------------------------------------------------------------------------
// Inputs: 0:x 1:embed 2:edge_index 3:node_id 4:tmp 5:eps 6:W1 7:b1 8:W2 9:b2
// ---------------------------------------------------------------------------
extern "C" void kernel_launch(void* const* d_in, const int* in_sizes, int n_in,
                              void* d_out, int out_size) {
    const float* embed = (const float*)d_in[1];
    const void*  ei    = d_in[2];
    const int*   nid   = (const int*)d_in[3];
    const float* tmp   = (const float*)d_in[4];
    const float* eps   = (const float*)d_in[5];
    const float* W1    = (const float*)d_in[6];
    const float* b1    = (const float*)d_in[7];
    const float* W2    = (const float*)d_in[8];
    const float* b2    = (const float*)d_in[9];
    float* out = (float*)d_out;

    static int attr_done = 0;
    if (!attr_done) {
        cudaFuncSetAttribute(gemm_kernel, cudaFuncAttributeMaxDynamicSharedMemorySize, SMEM_TOTAL);
        attr_done = 1;
    }

    detect_kernel<<<1, 1>>>((const int*)ei);
    splitW1_kernel<<<(640 * 64 / 4 + 255) / 256, 256>>>(W1);
    cvec_kernel<<<1, 512>>>(embed, W1, b1, nid);
    gemm_kernel<<<NTILES, 256, SMEM_TOTAL>>>(embed);
    edge_dot_kernel<<<1184, 256>>>(ei, W2);
    gate_kernel<<<(N_EDGES / 4 + 255) / 256, 256>>>(eps, tmp, b2, out);
}

// round 14
// speedup vs baseline: 1.8964x; 1.2679x over previous
#include <cuda_runtime.h>
#include <cuda_fp16.h>
#include <mma.h>
#include <cstdint>
using namespace nvcuda;

#define N_NODES   50000
#define EMB       320
#define HID       64
#define NH        128
#define N_EDGES   400000
#define NTILES    391          // ceil(50000/128)
#define KC        32
#define NCHUNK    (EMB / KC)   // 10

#define AP 40    // A smem pitch (fp16)
#define BP 136   // B smem pitch (fp16)

// dynamic smem layout (bytes)
#define SZ_A   (128 * AP * 2)          // 10240 per (stage, hi/lo)
#define SZ_B   (KC * BP * 2)           // 8704  per (stage, hi/lo)
#define SMEM_TOTAL (2 * (2 * SZ_A + 2 * SZ_B))   // 75776

// Scratch (no allocations allowed)
__device__ __align__(16) float g_P[N_NODES * NH];
__device__ __align__(16) float g_w[N_EDGES];
__device__ __align__(16) float g_cvec[HID];
__device__ __align__(16) __half g_W1h[640 * 64];
__device__ __align__(16) __half g_W1l[640 * 64];
__device__ int g_idx64;

// ---------------------------------------------------------------------------
// Kernel 0: detect edge_index element width (int32 vs int64, little-endian).
// Warp-parallel ballot version.
// ---------------------------------------------------------------------------
__global__ void detect_kernel(const int* __restrict__ ei_raw) {
    int lane = threadIdx.x;
    unsigned nz = __ballot_sync(0xffffffffu, ei_raw[2 * lane + 1] != 0);
    if (lane == 0) g_idx64 = (nz == 0u);
}

// ---------------------------------------------------------------------------
// Kernel S: W1[0:640] fp32 -> (hi, lo) fp16 split (tiny, one-shot).
// ---------------------------------------------------------------------------
__global__ __launch_bounds__(256) void splitW1_kernel(const float* __restrict__ W1) {
    int i = blockIdx.x * blockDim.x + threadIdx.x;
    if (i >= 640 * 64 / 4) return;
    float4 v = *reinterpret_cast<const float4*>(&W1[i * 4]);
    float a[4] = {v.x, v.y, v.z, v.w};
    __half h[4], l[4];
    #pragma unroll
    for (int q = 0; q < 4; q++) {
        h[q] = __float2half_rn(a[q]);
        l[q] = __float2half_rn(a[q] - __half2float(h[q]));
    }
    *reinterpret_cast<uint2*>(&g_W1h[i * 4]) = *reinterpret_cast<uint2*>(h);
    *reinterpret_cast<uint2*>(&g_W1l[i * 4]) = *reinterpret_cast<uint2*>(l);
}

// ---------------------------------------------------------------------------
// Kernel 1: wmma fp16 3-term GEMM, 2-stage smem double buffer (1 sync/chunk).
//   P[v,0:64]  = embed[v] @ W1[0:320,:]
//   P[v,64:128]= embed[v] @ W1[320:640,:]
// acc += Ah*Bh + Ah*Bl + Al*Bh  (missing Al*Bl ~ 2^-22 rel; fp16 11-bit splits).
// ---------------------------------------------------------------------------
__global__ __launch_bounds__(256, 2) void gemm_kernel(const float* __restrict__ embed) {
    extern __shared__ __align__(16) char sm[];
    auto AhP = [&](int s) { return reinterpret_cast<__half*>(sm + s * (2 * SZ_A + 2 * SZ_B)); };
    auto AlP = [&](int s) { return reinterpret_cast<__half*>(sm + s * (2 * SZ_A + 2 * SZ_B) + SZ_A); };
    auto BhP = [&](int s) { return reinterpret_cast<__half*>(sm + s * (2 * SZ_A + 2 * SZ_B) + 2 * SZ_A); };
    auto BlP = [&](int s) { return reinterpret_cast<__half*>(sm + s * (2 * SZ_A + 2 * SZ_B) + 2 * SZ_A + SZ_B); };

    const int tid = threadIdx.x;
    const int wid = tid >> 5;
    const int warp_m = wid & 1;
    const int warp_n = wid >> 1;
    const int m0 = blockIdx.x * 128;

    const int ar  = tid >> 1;
    const int aks = (tid & 1) * 16;
    const int a_gm = m0 + ar;
    const int bu4  = tid & 7;
    const int bhalf = (tid >> 3) & 1;
    const int bkr   = tid >> 4;

    wmma::fragment<wmma::accumulator, 16, 16, 16, float> acc[4][2];
    #pragma unroll
    for (int i = 0; i < 4; i++)
        #pragma unroll
        for (int j = 0; j < 2; j++)
            wmma::fill_fragment(acc[i][j], 0.f);

    float4 rA[4];
    uint4  rBh[2], rBl[2];

    auto loadA = [&](int k0) {
        if (a_gm < N_NODES) {
            const float* p = &embed[(size_t)a_gm * EMB + k0 + aks];
            #pragma unroll
            for (int q = 0; q < 4; q++)
                rA[q] = *reinterpret_cast<const float4*>(p + q * 4);
        } else {
            #pragma unroll
            for (int q = 0; q < 4; q++)
                rA[q] = make_float4(0.f, 0.f, 0.f, 0.f);
        }
    };
    auto loadB = [&](int k0) {
        #pragma unroll
        for (int p = 0; p < 2; p++) {
            size_t off = (size_t)(bhalf * 320 + k0 + bkr + p * 16) * 64 + bu4 * 8;
            rBh[p] = *reinterpret_cast<const uint4*>(&g_W1h[off]);
            rBl[p] = *reinterpret_cast<const uint4*>(&g_W1l[off]);
        }
    };
    auto sts = [&](int s) {
        __half* ah = AhP(s); __half* al = AlP(s);
        #pragma unroll
        for (int q = 0; q < 4; q++) {
            float a[4] = {rA[q].x, rA[q].y, rA[q].z, rA[q].w};
            __half h[4], l[4];
            #pragma unroll
            for (int i = 0; i < 4; i++) {
                h[i] = __float2half_rn(a[i]);
                l[i] = __float2half_rn(a[i] - __half2float(h[i]));
            }
            *reinterpret_cast<uint2*>(&ah[ar * AP + aks + q * 4]) = *reinterpret_cast<uint2*>(h);
            *reinterpret_cast<uint2*>(&al[ar * AP + aks + q * 4]) = *reinterpret_cast<uint2*>(l);
        }
        __half* bh = BhP(s); __half* bl = BlP(s);
        #pragma unroll
        for (int p = 0; p < 2; p++) {
            *reinterpret_cast<uint4*>(&bh[(bkr + p * 16) * BP + bhalf * 64 + bu4 * 8]) = rBh[p];
            *reinterpret_cast<uint4*>(&bl[(bkr + p * 16) * BP + bhalf * 64 + bu4 * 8]) = rBl[p];
        }
    };
    auto compute = [&](int s) {
        const __half* ah = AhP(s); const __half* al = AlP(s);
        const __half* bh = BhP(s); const __half* bl = BlP(s);
        #pragma unroll
        for (int ks = 0; ks < 2; ks++) {
            wmma::fragment<wmma::matrix_b, 16, 16, 16, __half, wmma::row_major> fbh[2], fbl[2];
            #pragma unroll
            for (int j = 0; j < 2; j++) {
                wmma::load_matrix_sync(fbh[j], &bh[(ks * 16) * BP + warp_n * 32 + j * 16], BP);
                wmma::load_matrix_sync(fbl[j], &bl[(ks * 16) * BP + warp_n * 32 + j * 16], BP);
            }
            #pragma unroll
            for (int i = 0; i < 4; i++) {
                wmma::fragment<wmma::matrix_a, 16, 16, 16, __half, wmma::row_major> fah, fal;
                wmma::load_matrix_sync(fah, &ah[(warp_m * 64 + i * 16) * AP + ks * 16], AP);
                wmma::load_matrix_sync(fal, &al[(warp_m * 64 + i * 16) * AP + ks * 16], AP);
                #pragma unroll
                for (int j = 0; j < 2; j++) {
                    wmma::mma_sync(acc[i][j], fah, fbh[j], acc[i][j]);
                    wmma::mma_sync(acc[i][j], fah, fbl[j], acc[i][j]);
                    wmma::mma_sync(acc[i][j], fal, fbh[j], acc[i][j]);
                }
            }
        }
    };

    loadA(0); loadB(0);
    sts(0);
    __syncthreads();
    loadA(KC); loadB(KC);

    for (int c = 0; c < NCHUNK; c++) {
        if (c + 1 < NCHUNK) sts((c + 1) & 1);
        if (c + 2 < NCHUNK) { loadA((c + 2) * KC); loadB((c + 2) * KC); }
        compute(c & 1);
        __syncthreads();
    }

    #pragma unroll
    for (int i = 0; i < 4; i++) {
        int gm = m0 + warp_m * 64 + i * 16;
        if (gm < N_NODES) {
            #pragma unroll
            for (int j = 0; j < 2; j++)
                wmma::store_matrix_sync(&g_P[(size_t)gm * NH + warp_n * 32 + j * 16],
                                        acc[i][j], NH, wmma::mem_row_major);
        }
    }
}

// ---------------------------------------------------------------------------
// Kernel 2: cvec — k-parallel (512 thr, 8 segments x 40 k, smem reduce).
// ---------------------------------------------------------------------------
__global__ __launch_bounds__(512) void cvec_kernel(const float* __restrict__ embed,
                                                   const float* __restrict__ W1,
                                                   const float* __restrict__ b1,
                                                   const int*   __restrict__ nid) {
    __shared__ float red[8][64];
    const int j = threadIdx.x & 63;
    const int s = threadIdx.x >> 6;
    const int n = nid[0];
    const float* er = &embed[(size_t)n * EMB];

    float sum = 0.f;
    #pragma unroll
    for (int q = 0; q < 40; q++) {
        int k = s * 40 + q;
        sum = fmaf(er[k], W1[(640 + k) * 64 + j], sum);
    }
    red[s][j] = sum;
    __syncthreads();
    if (s < 4) red[s][j] += red[s + 4][j];
    __syncthreads();
    if (s < 2) red[s][j] += red[s + 2][j];
    __syncthreads();
    if (s == 0) g_cvec[j] = red[0][j] + red[1][j] + b1[j];
}

// ---------------------------------------------------------------------------
// Kernel 3a: gather + dot (no transcendentals). 8 lanes/edge, 4 edges/warp.
// ---------------------------------------------------------------------------
__global__ __launch_bounds__(256) void edge_dot_kernel(const void* __restrict__ ei_raw,
                                                       const float* __restrict__ W2) {
    const int lane = threadIdx.x & 31;
    const int sub  = lane >> 3;
    const int j8   = lane & 7;
    const int warpGlobal = (blockIdx.x * blockDim.x + threadIdx.x) >> 5;
    const int nWarps = (gridDim.x * blockDim.x) >> 5;

    const float4 cv0 = *reinterpret_cast<const float4*>(&g_cvec[j8 * 8]);
    const float4 cv1 = *reinterpret_cast<const float4*>(&g_cvec[j8 * 8 + 4]);
    const float4 w20 = *reinterpret_cast<const float4*>(&W2[j8 * 8]);
    const float4 w21 = *reinterpret_cast<const float4*>(&W2[j8 * 8 + 4]);
    const int is64 = g_idx64;
    const long long* e64 = (const long long*)ei_raw;
    const int*       e32 = (const int*)ei_raw;

    for (int e = warpGlobal * 4 + sub; e < N_EDGES; e += nWarps * 4) {
        int col, row;
        if (is64) { col = (int)e64[e]; row = (int)e64[N_EDGES + e]; }
        else      { col = e32[e];      row = e32[N_EDGES + e]; }

        const float* Pc = &g_P[(size_t)col * NH + j8 * 8];
        const float* Pr = &g_P[(size_t)row * NH + 64 + j8 * 8];
        float4 a0 = *reinterpret_cast<const float4*>(Pc);
        float4 a1 = *reinterpret_cast<const float4*>(Pc + 4);
        float4 b0 = *reinterpret_cast<const float4*>(Pr);
        float4 b1 = *reinterpret_cast<const float4*>(Pr + 4);

        float p;
        p  = fmaxf(a0.x + b0.x + cv0.x, 0.f) * w20.x;
        p  = fmaf(fmaxf(a0.y + b0.y + cv0.y, 0.f), w20.y, p);
        p  = fmaf(fmaxf(a0.z + b0.z + cv0.z, 0.f), w20.z, p);
        p  = fmaf(fmaxf(a0.w + b0.w + cv0.w, 0.f), w20.w, p);
        p  = fmaf(fmaxf(a1.x + b1.x + cv1.x, 0.f), w21.x, p);
        p  = fmaf(fmaxf(a1.y + b1.y + cv1.y, 0.f), w21.y, p);
        p  = fmaf(fmaxf(a1.z + b1.z + cv1.z, 0.f), w21.z, p);
        p  = fmaf(fmaxf(a1.w + b1.w + cv1.w, 0.f), w21.w, p);

        p += __shfl_xor_sync(0xffffffffu, p, 4);
        p += __shfl_xor_sync(0xffffffffu, p, 2);
        p += __shfl_xor_sync(0xffffffffu, p, 1);

        if (j8 == 0) g_w[e] = p;
    }
}

// ---------------------------------------------------------------------------
// Kernel 3b: dense gate pass (tmp==1 fast path: no logs).
// ---------------------------------------------------------------------------
__global__ __launch_bounds__(256) void gate_kernel(const float* __restrict__ eps,
                                                   const float* __restrict__ tmp,
                                                   const float* __restrict__ b2,
                                                   float* __restrict__ out) {
    int i = blockIdx.x * blockDim.x + threadIdx.x;
    if (i * 4 >= N_EDGES) return;
    const float bias = 0.0001f, c1 = 1.f - 2.f * 0.0001f;
    float4 ev = *reinterpret_cast<const float4*>(&eps[i * 4]);
    float4 wv = *reinterpret_cast<const float4*>(&g_w[i * 4]);
    float t = tmp[0];
    float bb = b2[0];
    float e[4] = {fmaf(ev.x, c1, bias), fmaf(ev.y, c1, bias),
                  fmaf(ev.z, c1, bias), fmaf(ev.w, c1, bias)};
    float w[4] = {wv.x + bb, wv.y + bb, wv.z + bb, wv.w + bb};
    float o[4];
    if (t == 1.0f) {
        #pragma unroll
        for (int q = 0; q < 4; q++) {
            float s = __expf(-w[q]);
            o[q] = __fdividef(e[q], fmaf(s, 1.f - e[q], e[q]));
        }
    } else {
        float inv_t = __fdividef(1.f, t);
        #pragma unroll
        for (int q = 0; q < 4; q++) {
            float gate = (__logf(e[q]) - __logf(1.f - e[q]) + w[q]) * inv_t;
            o[q] = __fdividef(1.f, 1.f + __expf(-gate));
        }
    }
    *reinterpret_cast<float4*>(&out[i * 4]) = make_float4(o[0], o[1], o[2], o[3]);
}

// ---------------------------------------------------------------------------
// Inputs: 0:x 1:embed 2:edge_index 3:node_id 4:tmp 5:eps 6:W1 7:b1 8:W2 9:b2
// ---------------------------------------------------------------------------
extern "C" void kernel_launch(void* const* d_in, const int* in_sizes, int n_in,
                              void* d_out, int out_size) {
    const float* embed = (const float*)d_in[1];
    const void*  ei    = d_in[2];
    const int*   nid   = (const int*)d_in[3];
    const float* tmp   = (const float*)d_in[4];
    const float* eps   = (const float*)d_in[5];
    const float* W1    = (const float*)d_in[6];
    const float* b1    = (const float*)d_in[7];
    const float* W2    = (const float*)d_in[8];
    const float* b2    = (const float*)d_in[9];
    float* out = (float*)d_out;

    static int attr_done = 0;
    if (!attr_done) {
        cudaFuncSetAttribute(gemm_kernel, cudaFuncAttributeMaxDynamicSharedMemorySize, SMEM_TOTAL);
        attr_done = 1;
    }

    detect_kernel<<<1, 32>>>((const int*)ei);
    splitW1_kernel<<<(640 * 64 / 4 + 255) / 256, 256>>>(W1);
    cvec_kernel<<<1, 512>>>(embed, W1, b1, nid);
    gemm_kernel<<<NTILES, 256, SMEM_TOTAL>>>(embed);
    edge_dot_kernel<<<2368, 256>>>(ei, W2);
    gate_kernel<<<(N_EDGES / 4 + 255) / 256, 256>>>(eps, tmp, b2, out);
}

// round 15
// speedup vs baseline: 2.2419x; 1.1822x over previous
#include <cuda_runtime.h>
#include <cuda_fp16.h>
#include <mma.h>
#include <cstdint>
using namespace nvcuda;

#define N_NODES   50000
#define EMB       320
#define HID       64
#define NH        128
#define N_EDGES   400000
#define NTILES    391          // ceil(50000/128)
#define KC        32
#define NCHUNK    (EMB / KC)   // 10

#define AP 40    // A smem pitch (fp16)
#define BP 136   // B smem pitch (fp16)

// dynamic smem layout (bytes): per stage [Ah | Al | Bh]
#define SZ_A   (128 * AP * 2)          // 10240 per (stage, hi/lo)
#define SZ_B   (KC * BP * 2)           // 8704
#define STAGE  (2 * SZ_A + SZ_B)       // 29184
#define SMEM_TOTAL (2 * STAGE)         // 58368

// Scratch (no allocations allowed)
__device__ __align__(16) float g_P[N_NODES * NH];
__device__ __align__(16) float g_w[N_EDGES];
__device__ __align__(16) float g_cvec[HID];
__device__ __align__(16) __half g_W1h[640 * 64];
__device__ int g_idx64;

// ---------------------------------------------------------------------------
// Kernel 0: detect edge_index element width (int32 vs int64, little-endian).
// ---------------------------------------------------------------------------
__global__ void detect_kernel(const int* __restrict__ ei_raw) {
    int lane = threadIdx.x;
    unsigned nz = __ballot_sync(0xffffffffu, ei_raw[2 * lane + 1] != 0);
    if (lane == 0) g_idx64 = (nz == 0u);
}

// ---------------------------------------------------------------------------
// Kernel S: W1[0:640] fp32 -> fp16 (round-to-nearest), one-shot.
// ---------------------------------------------------------------------------
__global__ __launch_bounds__(256) void splitW1_kernel(const float* __restrict__ W1) {
    int i = blockIdx.x * blockDim.x + threadIdx.x;
    if (i >= 640 * 64 / 4) return;
    float4 v = *reinterpret_cast<const float4*>(&W1[i * 4]);
    __half h[4] = {__float2half_rn(v.x), __float2half_rn(v.y),
                   __float2half_rn(v.z), __float2half_rn(v.w)};
    *reinterpret_cast<uint2*>(&g_W1h[i * 4]) = *reinterpret_cast<uint2*>(h);
}

// ---------------------------------------------------------------------------
// Kernel 1: wmma fp16 2-term GEMM (A exact via hi+lo pair, B single fp16).
//   P[v,0:64]  = embed[v] @ W1[0:320,:]
//   P[v,64:128]= embed[v] @ W1[320:640,:]
// acc += Ah*Bh + Al*Bh.  Dropped A*(B-Bh) ~ 2^-12 pre-cancellation.
// 2-stage smem double buffer, 1 sync/chunk.
// ---------------------------------------------------------------------------
__global__ __launch_bounds__(256, 2) void gemm_kernel(const float* __restrict__ embed) {
    extern __shared__ __align__(16) char sm[];
    auto AhP = [&](int s) { return reinterpret_cast<__half*>(sm + s * STAGE); };
    auto AlP = [&](int s) { return reinterpret_cast<__half*>(sm + s * STAGE + SZ_A); };
    auto BhP = [&](int s) { return reinterpret_cast<__half*>(sm + s * STAGE + 2 * SZ_A); };

    const int tid = threadIdx.x;
    const int wid = tid >> 5;
    const int warp_m = wid & 1;
    const int warp_n = wid >> 1;
    const int m0 = blockIdx.x * 128;

    const int ar  = tid >> 1;
    const int aks = (tid & 1) * 16;
    const int a_gm = m0 + ar;
    const int bu4  = tid & 7;
    const int bhalf = (tid >> 3) & 1;
    const int bkr   = tid >> 4;

    wmma::fragment<wmma::accumulator, 16, 16, 16, float> acc[4][2];
    #pragma unroll
    for (int i = 0; i < 4; i++)
        #pragma unroll
        for (int j = 0; j < 2; j++)
            wmma::fill_fragment(acc[i][j], 0.f);

    float4 rA[4];
    uint4  rBh[2];

    auto loadA = [&](int k0) {
        if (a_gm < N_NODES) {
            const float* p = &embed[(size_t)a_gm * EMB + k0 + aks];
            #pragma unroll
            for (int q = 0; q < 4; q++)
                rA[q] = *reinterpret_cast<const float4*>(p + q * 4);
        } else {
            #pragma unroll
            for (int q = 0; q < 4; q++)
                rA[q] = make_float4(0.f, 0.f, 0.f, 0.f);
        }
    };
    auto loadB = [&](int k0) {
        #pragma unroll
        for (int p = 0; p < 2; p++) {
            size_t off = (size_t)(bhalf * 320 + k0 + bkr + p * 16) * 64 + bu4 * 8;
            rBh[p] = *reinterpret_cast<const uint4*>(&g_W1h[off]);
        }
    };
    auto sts = [&](int s) {
        __half* ah = AhP(s); __half* al = AlP(s);
        #pragma unroll
        for (int q = 0; q < 4; q++) {
            float a[4] = {rA[q].x, rA[q].y, rA[q].z, rA[q].w};
            __half h[4], l[4];
            #pragma unroll
            for (int i = 0; i < 4; i++) {
                h[i] = __float2half_rn(a[i]);
                l[i] = __float2half_rn(a[i] - __half2float(h[i]));
            }
            *reinterpret_cast<uint2*>(&ah[ar * AP + aks + q * 4]) = *reinterpret_cast<uint2*>(h);
            *reinterpret_cast<uint2*>(&al[ar * AP + aks + q * 4]) = *reinterpret_cast<uint2*>(l);
        }
        __half* bh = BhP(s);
        #pragma unroll
        for (int p = 0; p < 2; p++)
            *reinterpret_cast<uint4*>(&bh[(bkr + p * 16) * BP + bhalf * 64 + bu4 * 8]) = rBh[p];
    };
    auto compute = [&](int s) {
        const __half* ah = AhP(s); const __half* al = AlP(s);
        const __half* bh = BhP(s);
        #pragma unroll
        for (int ks = 0; ks < 2; ks++) {
            wmma::fragment<wmma::matrix_b, 16, 16, 16, __half, wmma::row_major> fbh[2];
            #pragma unroll
            for (int j = 0; j < 2; j++)
                wmma::load_matrix_sync(fbh[j], &bh[(ks * 16) * BP + warp_n * 32 + j * 16], BP);
            #pragma unroll
            for (int i = 0; i < 4; i++) {
                wmma::fragment<wmma::matrix_a, 16, 16, 16, __half, wmma::row_major> fah, fal;
                wmma::load_matrix_sync(fah, &ah[(warp_m * 64 + i * 16) * AP + ks * 16], AP);
                wmma::load_matrix_sync(fal, &al[(warp_m * 64 + i * 16) * AP + ks * 16], AP);
                #pragma unroll
                for (int j = 0; j < 2; j++) {
                    wmma::mma_sync(acc[i][j], fah, fbh[j], acc[i][j]);
                    wmma::mma_sync(acc[i][j], fal, fbh[j], acc[i][j]);
                }
            }
        }
    };

    loadA(0); loadB(0);
    sts(0);
    __syncthreads();
    loadA(KC); loadB(KC);

    for (int c = 0; c < NCHUNK; c++) {
        if (c + 1 < NCHUNK) sts((c + 1) & 1);
        if (c + 2 < NCHUNK) { loadA((c + 2) * KC); loadB((c + 2) * KC); }
        compute(c & 1);
        __syncthreads();
    }

    #pragma unroll
    for (int i = 0; i < 4; i++) {
        int gm = m0 + warp_m * 64 + i * 16;
        if (gm < N_NODES) {
            #pragma unroll
            for (int j = 0; j < 2; j++)
                wmma::store_matrix_sync(&g_P[(size_t)gm * NH + warp_n * 32 + j * 16],
                                        acc[i][j], NH, wmma::mem_row_major);
        }
    }
}

// ---------------------------------------------------------------------------
// Kernel 2: cvec — k-parallel (512 thr, 8 segments x 40 k, smem reduce). Exact fp32.
// ---------------------------------------------------------------------------
__global__ __launch_bounds__(512) void cvec_kernel(const float* __restrict__ embed,
                                                   const float* __restrict__ W1,
                                                   const float* __restrict__ b1,
                                                   const int*   __restrict__ nid) {
    __shared__ float red[8][64];
    const int j = threadIdx.x & 63;
    const int s = threadIdx.x >> 6;
    const int n = nid[0];
    const float* er = &embed[(size_t)n * EMB];

    float sum = 0.f;
    #pragma unroll
    for (int q = 0; q < 40; q++) {
        int k = s * 40 + q;
        sum = fmaf(er[k], W1[(640 + k) * 64 + j], sum);
    }
    red[s][j] = sum;
    __syncthreads();
    if (s < 4) red[s][j] += red[s + 4][j];
    __syncthreads();
    if (s < 2) red[s][j] += red[s + 2][j];
    __syncthreads();
    if (s == 0) g_cvec[j] = red[0][j] + red[1][j] + b1[j];
}

// ---------------------------------------------------------------------------
// Kernel 3a: gather + dot (no transcendentals). 8 lanes/edge, 4 edges/warp.
// ---------------------------------------------------------------------------
__global__ __launch_bounds__(256) void edge_dot_kernel(const void* __restrict__ ei_raw,
                                                       const float* __restrict__ W2) {
    const int lane = threadIdx.x & 31;
    const int sub  = lane >> 3;
    const int j8   = lane & 7;
    const int warpGlobal = (blockIdx.x * blockDim.x + threadIdx.x) >> 5;
    const int nWarps = (gridDim.x * blockDim.x) >> 5;

    const float4 cv0 = *reinterpret_cast<const float4*>(&g_cvec[j8 * 8]);
    const float4 cv1 = *reinterpret_cast<const float4*>(&g_cvec[j8 * 8 + 4]);
    const float4 w20 = *reinterpret_cast<const float4*>(&W2[j8 * 8]);
    const float4 w21 = *reinterpret_cast<const float4*>(&W2[j8 * 8 + 4]);
    const int is64 = g_idx64;
    const long long* e64 = (const long long*)ei_raw;
    const int*       e32 = (const int*)ei_raw;

    for (int e = warpGlobal * 4 + sub; e < N_EDGES; e += nWarps * 4) {
        int col, row;
        if (is64) { col = (int)e64[e]; row = (int)e64[N_EDGES + e]; }
        else      { col = e32[e];      row = e32[N_EDGES + e]; }

        const float* Pc = &g_P[(size_t)col * NH + j8 * 8];
        const float* Pr = &g_P[(size_t)row * NH + 64 + j8 * 8];
        float4 a0 = *reinterpret_cast<const float4*>(Pc);
        float4 a1 = *reinterpret_cast<const float4*>(Pc + 4);
        float4 b0 = *reinterpret_cast<const float4*>(Pr);
        float4 b1 = *reinterpret_cast<const float4*>(Pr + 4);

        float p;
        p  = fmaxf(a0.x + b0.x + cv0.x, 0.f) * w20.x;
        p  = fmaf(fmaxf(a0.y + b0.y + cv0.y, 0.f), w20.y, p);
        p  = fmaf(fmaxf(a0.z + b0.z + cv0.z, 0.f), w20.z, p);
        p  = fmaf(fmaxf(a0.w + b0.w + cv0.w, 0.f), w20.w, p);
        p  = fmaf(fmaxf(a1.x + b1.x + cv1.x, 0.f), w21.x, p);
        p  = fmaf(fmaxf(a1.y + b1.y + cv1.y, 0.f), w21.y, p);
        p  = fmaf(fmaxf(a1.z + b1.z + cv1.z, 0.f), w21.z, p);
        p  = fmaf(fmaxf(a1.w + b1.w + cv1.w, 0.f), w21.w, p);

        p += __shfl_xor_sync(0xffffffffu, p, 4);
        p += __shfl_xor_sync(0xffffffffu, p, 2);
        p += __shfl_xor_sync(0xffffffffu, p, 1);

        if (j8 == 0) g_w[e] = p;
    }
}

// ---------------------------------------------------------------------------
// Kernel 3b: dense gate pass (tmp==1 fast path: no logs).
// ---------------------------------------------------------------------------
__global__ __launch_bounds__(256) void gate_kernel(const float* __restrict__ eps,
                                                   const float* __restrict__ tmp,
                                                   const float* __restrict__ b2,
                                                   float* __restrict__ out) {
    int i = blockIdx.x * blockDim.x + threadIdx.x;
    if (i * 4 >= N_EDGES) return;
    const float bias = 0.0001f, c1 = 1.f - 2.f * 0.0001f;
    float4 ev = *reinterpret_cast<const float4*>(&eps[i * 4]);
    float4 wv = *reinterpret_cast<const float4*>(&g_w[i * 4]);
    float t = tmp[0];
    float bb = b2[0];
    float e[4] = {fmaf(ev.x, c1, bias), fmaf(ev.y, c1, bias),
                  fmaf(ev.z, c1, bias), fmaf(ev.w, c1, bias)};
    float w[4] = {wv.x + bb, wv.y + bb, wv.z + bb, wv.w + bb};
    float o[4];
    if (t == 1.0f) {
        #pragma unroll
        for (int q = 0; q < 4; q++) {
            float s = __expf(-w[q]);
            o[q] = __fdividef(e[q], fmaf(s, 1.f - e[q], e[q]));
        }
    } else {
        float inv_t = __fdividef(1.f, t);
        #pragma unroll
        for (int q = 0; q < 4; q++) {
            float gate = (__logf(e[q]) - __logf(1.f - e[q]) + w[q]) * inv_t;
            o[q] = __fdividef(1.f, 1.f + __expf(-gate));
        }
    }
    *reinterpret_cast<float4*>(&out[i * 4]) = make_float4(o[0], o[1], o[2], o[3]);
}

// ---------------------------------------------------------------------------
// Inputs: 0:x 1:embed 2:edge_index 3:node_id 4:tmp 5:eps 6:W1 7:b1 8:W2 9:b2
// ---------------------------------------------------------------------------
extern "C" void kernel_launch(void* const* d_in, const int* in_sizes, int n_in,
                              void* d_out, int out_size) {
    const float* embed = (const float*)d_in[1];
    const void*  ei    = d_in[2];
    const int*   nid   = (const int*)d_in[3];
    const float* tmp   = (const float*)d_in[4];
    const float* eps   = (const float*)d_in[5];
    const float* W1    = (const float*)d_in[6];
    const float* b1    = (const float*)d_in[7];
    const float* W2    = (const float*)d_in[8];
    const float* b2    = (const float*)d_in[9];
    float* out = (float*)d_out;

    static int attr_done = 0;
    if (!attr_done) {
        cudaFuncSetAttribute(gemm_kernel, cudaFuncAttributeMaxDynamicSharedMemorySize, SMEM_TOTAL);
        attr_done = 1;
    }

    detect_kernel<<<1, 32>>>((const int*)ei);
    splitW1_kernel<<<(640 * 64 / 4 + 255) / 256, 256>>>(W1);
    cvec_kernel<<<1, 512>>>(embed, W1, b1, nid);
    gemm_kernel<<<NTILES, 256, SMEM_TOTAL>>>(embed);
    edge_dot_kernel<<<2368, 256>>>(ei, W2);
    gate_kernel<<<(N_EDGES / 4 + 255) / 256, 256>>>(eps, tmp, b2, out);
}

// round 16
// speedup vs baseline: 2.5232x; 1.1255x over previous
#include <cuda_runtime.h>
#include <cuda_fp16.h>
#include <mma.h>
#include <cstdint>
using namespace nvcuda;

#define N_NODES   50000
#define EMB       320
#define HID       64
#define NH        128
#define N_EDGES   400000
#define NTILES    391          // ceil(50000/128)
#define KC        32
#define NCHUNK    (EMB / KC)   // 10

#define AP 40    // A smem pitch (fp16)
#define BP 136   // B smem pitch (fp16)

// dynamic smem layout (bytes): per stage [Ah | Bh]
#define SZ_A   (128 * AP * 2)          // 10240
#define SZ_B   (KC * BP * 2)           // 8704
#define STAGE  (SZ_A + SZ_B)           // 18944
#define SMEM_TOTAL (2 * STAGE)         // 37888

// Scratch (no allocations allowed)
__device__ __align__(16) float g_P[N_NODES * NH];
__device__ __align__(16) float g_w[N_EDGES];
__device__ __align__(16) float g_cvec[HID];
__device__ __align__(16) __half g_W1h[640 * 64];
__device__ int g_idx64;

// ---------------------------------------------------------------------------
// Kernel 0: detect edge_index element width (int32 vs int64, little-endian).
// ---------------------------------------------------------------------------
__global__ void detect_kernel(const int* __restrict__ ei_raw) {
    int lane = threadIdx.x;
    unsigned nz = __ballot_sync(0xffffffffu, ei_raw[2 * lane + 1] != 0);
    if (lane == 0) g_idx64 = (nz == 0u);
}

// ---------------------------------------------------------------------------
// Kernel S: W1[0:640] fp32 -> fp16 (round-to-nearest), one-shot.
// ---------------------------------------------------------------------------
__global__ __launch_bounds__(256) void splitW1_kernel(const float* __restrict__ W1) {
    int i = blockIdx.x * blockDim.x + threadIdx.x;
    if (i >= 640 * 64 / 4) return;
    float4 v = *reinterpret_cast<const float4*>(&W1[i * 4]);
    __half h[4] = {__float2half_rn(v.x), __float2half_rn(v.y),
                   __float2half_rn(v.z), __float2half_rn(v.w)};
    *reinterpret_cast<uint2*>(&g_W1h[i * 4]) = *reinterpret_cast<uint2*>(h);
}

// ---------------------------------------------------------------------------
// Kernel 1: pure fp16 wmma GEMM (1 MMA term), fp32 accumulate.
//   P[v,0:64]  = embed[v] @ W1[0:320,:]
//   P[v,64:128]= embed[v] @ W1[320:640,:]
// Rounding error ~5e-5 rel (measured calibration from R15), vs 1e-3 gate.
// 2-stage smem double buffer, 1 sync/chunk.
// ---------------------------------------------------------------------------
__global__ __launch_bounds__(256, 2) void gemm_kernel(const float* __restrict__ embed) {
    extern __shared__ __align__(16) char sm[];
    auto AhP = [&](int s) { return reinterpret_cast<__half*>(sm + s * STAGE); };
    auto BhP = [&](int s) { return reinterpret_cast<__half*>(sm + s * STAGE + SZ_A); };

    const int tid = threadIdx.x;
    const int wid = tid >> 5;
    const int warp_m = wid & 1;
    const int warp_n = wid >> 1;
    const int m0 = blockIdx.x * 128;

    const int ar  = tid >> 1;
    const int aks = (tid & 1) * 16;
    const int a_gm = m0 + ar;
    const int bu4  = tid & 7;
    const int bhalf = (tid >> 3) & 1;
    const int bkr   = tid >> 4;

    wmma::fragment<wmma::accumulator, 16, 16, 16, float> acc[4][2];
    #pragma unroll
    for (int i = 0; i < 4; i++)
        #pragma unroll
        for (int j = 0; j < 2; j++)
            wmma::fill_fragment(acc[i][j], 0.f);

    float4 rA[4];
    uint4  rBh[2];

    auto loadA = [&](int k0) {
        if (a_gm < N_NODES) {
            const float* p = &embed[(size_t)a_gm * EMB + k0 + aks];
            #pragma unroll
            for (int q = 0; q < 4; q++)
                rA[q] = *reinterpret_cast<const float4*>(p + q * 4);
        } else {
            #pragma unroll
            for (int q = 0; q < 4; q++)
                rA[q] = make_float4(0.f, 0.f, 0.f, 0.f);
        }
    };
    auto loadB = [&](int k0) {
        #pragma unroll
        for (int p = 0; p < 2; p++) {
            size_t off = (size_t)(bhalf * 320 + k0 + bkr + p * 16) * 64 + bu4 * 8;
            rBh[p] = *reinterpret_cast<const uint4*>(&g_W1h[off]);
        }
    };
    auto sts = [&](int s) {
        __half* ah = AhP(s);
        #pragma unroll
        for (int q = 0; q < 4; q++) {
            __half h[4] = {__float2half_rn(rA[q].x), __float2half_rn(rA[q].y),
                           __float2half_rn(rA[q].z), __float2half_rn(rA[q].w)};
            *reinterpret_cast<uint2*>(&ah[ar * AP + aks + q * 4]) = *reinterpret_cast<uint2*>(h);
        }
        __half* bh = BhP(s);
        #pragma unroll
        for (int p = 0; p < 2; p++)
            *reinterpret_cast<uint4*>(&bh[(bkr + p * 16) * BP + bhalf * 64 + bu4 * 8]) = rBh[p];
    };
    auto compute = [&](int s) {
        const __half* ah = AhP(s);
        const __half* bh = BhP(s);
        #pragma unroll
        for (int ks = 0; ks < 2; ks++) {
            wmma::fragment<wmma::matrix_b, 16, 16, 16, __half, wmma::row_major> fbh[2];
            #pragma unroll
            for (int j = 0; j < 2; j++)
                wmma::load_matrix_sync(fbh[j], &bh[(ks * 16) * BP + warp_n * 32 + j * 16], BP);
            #pragma unroll
            for (int i = 0; i < 4; i++) {
                wmma::fragment<wmma::matrix_a, 16, 16, 16, __half, wmma::row_major> fah;
                wmma::load_matrix_sync(fah, &ah[(warp_m * 64 + i * 16) * AP + ks * 16], AP);
                #pragma unroll
                for (int j = 0; j < 2; j++)
                    wmma::mma_sync(acc[i][j], fah, fbh[j], acc[i][j]);
            }
        }
    };

    loadA(0); loadB(0);
    sts(0);
    __syncthreads();
    loadA(KC); loadB(KC);

    for (int c = 0; c < NCHUNK; c++) {
        if (c + 1 < NCHUNK) sts((c + 1) & 1);
        if (c + 2 < NCHUNK) { loadA((c + 2) * KC); loadB((c + 2) * KC); }
        compute(c & 1);
        __syncthreads();
    }

    #pragma unroll
    for (int i = 0; i < 4; i++) {
        int gm = m0 + warp_m * 64 + i * 16;
        if (gm < N_NODES) {
            #pragma unroll
            for (int j = 0; j < 2; j++)
                wmma::store_matrix_sync(&g_P[(size_t)gm * NH + warp_n * 32 + j * 16],
                                        acc[i][j], NH, wmma::mem_row_major);
        }
    }
}

// ---------------------------------------------------------------------------
// Kernel 2: cvec — k-parallel (512 thr, 8 segments x 40 k, smem reduce). Exact fp32.
// ---------------------------------------------------------------------------
__global__ __launch_bounds__(512) void cvec_kernel(const float* __restrict__ embed,
                                                   const float* __restrict__ W1,
                                                   const float* __restrict__ b1,
                                                   const int*   __restrict__ nid) {
    __shared__ float red[8][64];
    const int j = threadIdx.x & 63;
    const int s = threadIdx.x >> 6;
    const int n = nid[0];
    const float* er = &embed[(size_t)n * EMB];

    float sum = 0.f;
    #pragma unroll
    for (int q = 0; q < 40; q++) {
        int k = s * 40 + q;
        sum = fmaf(er[k], W1[(640 + k) * 64 + j], sum);
    }
    red[s][j] = sum;
    __syncthreads();
    if (s < 4) red[s][j] += red[s + 4][j];
    __syncthreads();
    if (s < 2) red[s][j] += red[s + 2][j];
    __syncthreads();
    if (s == 0) g_cvec[j] = red[0][j] + red[1][j] + b1[j];
}

// ---------------------------------------------------------------------------
// Kernel 3a: gather + dot (no transcendentals). 8 lanes/edge, 4 edges/warp.
// ---------------------------------------------------------------------------
__global__ __launch_bounds__(256) void edge_dot_kernel(const void* __restrict__ ei_raw,
                                                       const float* __restrict__ W2) {
    const int lane = threadIdx.x & 31;
    const int sub  = lane >> 3;
    const int j8   = lane & 7;
    const int warpGlobal = (blockIdx.x * blockDim.x + threadIdx.x) >> 5;
    const int nWarps = (gridDim.x * blockDim.x) >> 5;

    const float4 cv0 = *reinterpret_cast<const float4*>(&g_cvec[j8 * 8]);
    const float4 cv1 = *reinterpret_cast<const float4*>(&g_cvec[j8 * 8 + 4]);
    const float4 w20 = *reinterpret_cast<const float4*>(&W2[j8 * 8]);
    const float4 w21 = *reinterpret_cast<const float4*>(&W2[j8 * 8 + 4]);
    const int is64 = g_idx64;
    const long long* e64 = (const long long*)ei_raw;
    const int*       e32 = (const int*)ei_raw;

    for (int e = warpGlobal * 4 + sub; e < N_EDGES; e += nWarps * 4) {
        int col, row;
        if (is64) { col = (int)e64[e]; row = (int)e64[N_EDGES + e]; }
        else      { col = e32[e];      row = e32[N_EDGES + e]; }

        const float* Pc = &g_P[(size_t)col * NH + j8 * 8];
        const float* Pr = &g_P[(size_t)row * NH + 64 + j8 * 8];
        float4 a0 = *reinterpret_cast<const float4*>(Pc);
        float4 a1 = *reinterpret_cast<const float4*>(Pc + 4);
        float4 b0 = *reinterpret_cast<const float4*>(Pr);
        float4 b1 = *reinterpret_cast<const float4*>(Pr + 4);

        float p;
        p  = fmaxf(a0.x + b0.x + cv0.x, 0.f) * w20.x;
        p  = fmaf(fmaxf(a0.y + b0.y + cv0.y, 0.f), w20.y, p);
        p  = fmaf(fmaxf(a0.z + b0.z + cv0.z, 0.f), w20.z, p);
        p  = fmaf(fmaxf(a0.w + b0.w + cv0.w, 0.f), w20.w, p);
        p  = fmaf(fmaxf(a1.x + b1.x + cv1.x, 0.f), w21.x, p);
        p  = fmaf(fmaxf(a1.y + b1.y + cv1.y, 0.f), w21.y, p);
        p  = fmaf(fmaxf(a1.z + b1.z + cv1.z, 0.f), w21.z, p);
        p  = fmaf(fmaxf(a1.w + b1.w + cv1.w, 0.f), w21.w, p);

        p += __shfl_xor_sync(0xffffffffu, p, 4);
        p += __shfl_xor_sync(0xffffffffu, p, 2);
        p += __shfl_xor_sync(0xffffffffu, p, 1);

        if (j8 == 0) g_w[e] = p;
    }
}

// ---------------------------------------------------------------------------
// Kernel 3b: dense gate pass (tmp==1 fast path: no logs).
// ---------------------------------------------------------------------------
__global__ __launch_bounds__(256) void gate_kernel(const float* __restrict__ eps,
                                                   const float* __restrict__ tmp,
                                                   const float* __restrict__ b2,
                                                   float* __restrict__ out) {
    int i = blockIdx.x * blockDim.x + threadIdx.x;
    if (i * 4 >= N_EDGES) return;
    const float bias = 0.0001f, c1 = 1.f - 2.f * 0.0001f;
    float4 ev = *reinterpret_cast<const float4*>(&eps[i * 4]);
    float4 wv = *reinterpret_cast<const float4*>(&g_w[i * 4]);
    float t = tmp[0];
    float bb = b2[0];
    float e[4] = {fmaf(ev.x, c1, bias), fmaf(ev.y, c1, bias),
                  fmaf(ev.z, c1, bias), fmaf(ev.w, c1, bias)};
    float w[4] = {wv.x + bb, wv.y + bb, wv.z + bb, wv.w + bb};
    float o[4];
    if (t == 1.0f) {
        #pragma unroll
        for (int q = 0; q < 4; q++) {
            float s = __expf(-w[q]);
            o[q] = __fdividef(e[q], fmaf(s, 1.f - e[q], e[q]));
        }
    } else {
        float inv_t = __fdividef(1.f, t);
        #pragma unroll
        for (int q = 0; q < 4; q++) {
            float gate = (__logf(e[q]) - __logf(1.f - e[q]) + w[q]) * inv_t;
            o[q] = __fdividef(1.f, 1.f + __expf(-gate));
        }
    }
    *reinterpret_cast<float4*>(&out[i * 4]) = make_float4(o[0], o[1], o[2], o[3]);
}

// ---------------------------------------------------------------------------
// Inputs: 0:x 1:embed 2:edge_index 3:node_id 4:tmp 5:eps 6:W1 7:b1 8:W2 9:b2
// ---------------------------------------------------------------------------
extern "C" void kernel_launch(void* const* d_in, const int* in_sizes, int n_in,
                              void* d_out, int out_size) {
    const float* embed = (const float*)d_in[1];
    const void*  ei    = d_in[2];
    const int*   nid   = (const int*)d_in[3];
    const float* tmp   = (const float*)d_in[4];
    const float* eps   = (const float*)d_in[5];
    const float* W1    = (const float*)d_in[6];
    const float* b1    = (const float*)d_in[7];
    const float* W2    = (const float*)d_in[8];
    const float* b2    = (const float*)d_in[9];
    float* out = (float*)d_out;

    static int attr_done = 0;
    if (!attr_done) {
        cudaFuncSetAttribute(gemm_kernel, cudaFuncAttributeMaxDynamicSharedMemorySize, SMEM_TOTAL);
        attr_done = 1;
    }

    detect_kernel<<<1, 32>>>((const int*)ei);
    splitW1_kernel<<<(640 * 64 / 4 + 255) / 256, 256>>>(W1);
    cvec_kernel<<<1, 512>>>(embed, W1, b1, nid);
    gemm_kernel<<<NTILES, 256, SMEM_TOTAL>>>(embed);
    edge_dot_kernel<<<2368, 256>>>(ei, W2);
    gate_kernel<<<(N_EDGES / 4 + 255) / 256, 256>>>(eps, tmp, b2, out);
}

// round 17
// speedup vs baseline: 2.5363x; 1.0052x over previous
#include <cuda_runtime.h>
#include <cuda_fp16.h>
#include <mma.h>
#include <cstdint>
using namespace nvcuda;

#define N_NODES   50000
#define EMB       320
#define HID       64
#define NH        128
#define N_EDGES   400000
#define NTILES    391          // ceil(50000/128)
#define KC        32
#define NCHUNK    (EMB / KC)   // 10

#define AP 40    // A smem pitch (fp16)
#define BP 136   // B smem pitch (fp16)

// dynamic smem layout (bytes): per stage [Ah | Bh]
#define SZ_A   (128 * AP * 2)          // 10240
#define SZ_B   (KC * BP * 2)           // 8704
#define STAGE  (SZ_A + SZ_B)           // 18944
#define SMEM_TOTAL (2 * STAGE)         // 37888

// Scratch (no allocations allowed)
__device__ __align__(16) float g_P[N_NODES * NH];
__device__ __align__(16) float g_cvec[HID];
__device__ __align__(16) __half g_W1h[640 * 64];
__device__ int g_idx64;

// ---------------------------------------------------------------------------
// Kernel P: fused prep. Block 0: detect (warp 0) + cvec (all 256 threads,
// 4 segments x 80 k). Blocks 1..40: W1[0:640] fp32 -> fp16.
// ---------------------------------------------------------------------------
__global__ __launch_bounds__(256) void prep_kernel(const float* __restrict__ embed,
                                                   const float* __restrict__ W1,
                                                   const float* __restrict__ b1,
                                                   const int*   __restrict__ nid,
                                                   const int*   __restrict__ ei_raw) {
    if (blockIdx.x == 0) {
        // detect edge_index width (warp 0)
        if (threadIdx.x < 32) {
            unsigned nz = __ballot_sync(0xffffffffu, ei_raw[2 * threadIdx.x + 1] != 0);
            if (threadIdx.x == 0) g_idx64 = (nz == 0u);
        }
        // cvec: j = tid & 63, segment s = tid >> 6 (4 segs x 80 k)
        __shared__ float red[4][64];
        const int j = threadIdx.x & 63;
        const int s = threadIdx.x >> 6;
        const int n = nid[0];
        const float* er = &embed[(size_t)n * EMB];
        float sum = 0.f;
        #pragma unroll
        for (int q = 0; q < 80; q++) {
            int k = s * 80 + q;
            sum = fmaf(er[k], W1[(640 + k) * 64 + j], sum);
        }
        red[s][j] = sum;
        __syncthreads();
        if (s < 2) red[s][j] += red[s + 2][j];
        __syncthreads();
        if (s == 0) g_cvec[j] = red[0][j] + red[1][j] + b1[j];
    } else {
        int i = (blockIdx.x - 1) * blockDim.x + threadIdx.x;   // 0 .. 10239
        float4 v = *reinterpret_cast<const float4*>(&W1[i * 4]);
        __half h[4] = {__float2half_rn(v.x), __float2half_rn(v.y),
                       __float2half_rn(v.z), __float2half_rn(v.w)};
        *reinterpret_cast<uint2*>(&g_W1h[i * 4]) = *reinterpret_cast<uint2*>(h);
    }
}

// ---------------------------------------------------------------------------
// Kernel 1: pure fp16 wmma GEMM (1 MMA term), fp32 accumulate. (R16-proven)
//   P[v,0:64]  = embed[v] @ W1[0:320,:]
//   P[v,64:128]= embed[v] @ W1[320:640,:]
// ---------------------------------------------------------------------------
__global__ __launch_bounds__(256, 2) void gemm_kernel(const float* __restrict__ embed) {
    extern __shared__ __align__(16) char sm[];
    auto AhP = [&](int s) { return reinterpret_cast<__half*>(sm + s * STAGE); };
    auto BhP = [&](int s) { return reinterpret_cast<__half*>(sm + s * STAGE + SZ_A); };

    const int tid = threadIdx.x;
    const int wid = tid >> 5;
    const int warp_m = wid & 1;
    const int warp_n = wid >> 1;
    const int m0 = blockIdx.x * 128;

    const int ar  = tid >> 1;
    const int aks = (tid & 1) * 16;
    const int a_gm = m0 + ar;
    const int bu4  = tid & 7;
    const int bhalf = (tid >> 3) & 1;
    const int bkr   = tid >> 4;

    wmma::fragment<wmma::accumulator, 16, 16, 16, float> acc[4][2];
    #pragma unroll
    for (int i = 0; i < 4; i++)
        #pragma unroll
        for (int j = 0; j < 2; j++)
            wmma::fill_fragment(acc[i][j], 0.f);

    float4 rA[4];
    uint4  rBh[2];

    auto loadA = [&](int k0) {
        if (a_gm < N_NODES) {
            const float* p = &embed[(size_t)a_gm * EMB + k0 + aks];
            #pragma unroll
            for (int q = 0; q < 4; q++)
                rA[q] = *reinterpret_cast<const float4*>(p + q * 4);
        } else {
            #pragma unroll
            for (int q = 0; q < 4; q++)
                rA[q] = make_float4(0.f, 0.f, 0.f, 0.f);
        }
    };
    auto loadB = [&](int k0) {
        #pragma unroll
        for (int p = 0; p < 2; p++) {
            size_t off = (size_t)(bhalf * 320 + k0 + bkr + p * 16) * 64 + bu4 * 8;
            rBh[p] = *reinterpret_cast<const uint4*>(&g_W1h[off]);
        }
    };
    auto sts = [&](int s) {
        __half* ah = AhP(s);
        #pragma unroll
        for (int q = 0; q < 4; q++) {
            __half h[4] = {__float2half_rn(rA[q].x), __float2half_rn(rA[q].y),
                           __float2half_rn(rA[q].z), __float2half_rn(rA[q].w)};
            *reinterpret_cast<uint2*>(&ah[ar * AP + aks + q * 4]) = *reinterpret_cast<uint2*>(h);
        }
        __half* bh = BhP(s);
        #pragma unroll
        for (int p = 0; p < 2; p++)
            *reinterpret_cast<uint4*>(&bh[(bkr + p * 16) * BP + bhalf * 64 + bu4 * 8]) = rBh[p];
    };
    auto compute = [&](int s) {
        const __half* ah = AhP(s);
        const __half* bh = BhP(s);
        #pragma unroll
        for (int ks = 0; ks < 2; ks++) {
            wmma::fragment<wmma::matrix_b, 16, 16, 16, __half, wmma::row_major> fbh[2];
            #pragma unroll
            for (int j = 0; j < 2; j++)
                wmma::load_matrix_sync(fbh[j], &bh[(ks * 16) * BP + warp_n * 32 + j * 16], BP);
            #pragma unroll
            for (int i = 0; i < 4; i++) {
                wmma::fragment<wmma::matrix_a, 16, 16, 16, __half, wmma::row_major> fah;
                wmma::load_matrix_sync(fah, &ah[(warp_m * 64 + i * 16) * AP + ks * 16], AP);
                #pragma unroll
                for (int j = 0; j < 2; j++)
                    wmma::mma_sync(acc[i][j], fah, fbh[j], acc[i][j]);
            }
        }
    };

    loadA(0); loadB(0);
    sts(0);
    __syncthreads();
    loadA(KC); loadB(KC);

    for (int c = 0; c < NCHUNK; c++) {
        if (c + 1 < NCHUNK) sts((c + 1) & 1);
        if (c + 2 < NCHUNK) { loadA((c + 2) * KC); loadB((c + 2) * KC); }
        compute(c & 1);
        __syncthreads();
    }

    #pragma unroll
    for (int i = 0; i < 4; i++) {
        int gm = m0 + warp_m * 64 + i * 16;
        if (gm < N_NODES) {
            #pragma unroll
            for (int j = 0; j < 2; j++)
                wmma::store_matrix_sync(&g_P[(size_t)gm * NH + warp_n * 32 + j * 16],
                                        acc[i][j], NH, wmma::mem_row_major);
        }
    }
}

// ---------------------------------------------------------------------------
// Kernel 3: fused edge gather+dot+gate. 8 lanes/edge, 2 edges per 8-lane
// group per iteration (x2 unroll, batched loads to hide L2 latency).
// ---------------------------------------------------------------------------
__global__ __launch_bounds__(256) void edge_kernel(const void* __restrict__ ei_raw,
                                                   const float* __restrict__ W2,
                                                   const float* __restrict__ eps,
                                                   const float* __restrict__ tmp,
                                                   const float* __restrict__ b2,
                                                   float* __restrict__ out) {
    const int lane = threadIdx.x & 31;
    const int sub  = lane >> 3;           // 8-lane group id (0..3)
    const int j8   = lane & 7;
    const int warpGlobal = (blockIdx.x * blockDim.x + threadIdx.x) >> 5;
    const int nWarps = (gridDim.x * blockDim.x) >> 5;

    const float4 cv0 = *reinterpret_cast<const float4*>(&g_cvec[j8 * 8]);
    const float4 cv1 = *reinterpret_cast<const float4*>(&g_cvec[j8 * 8 + 4]);
    const float4 w20 = *reinterpret_cast<const float4*>(&W2[j8 * 8]);
    const float4 w21 = *reinterpret_cast<const float4*>(&W2[j8 * 8 + 4]);
    const int is64 = g_idx64;
    const long long* e64 = (const long long*)ei_raw;
    const int*       e32 = (const int*)ei_raw;
    const float t   = tmp[0];
    const float bb  = b2[0];
    const float bias = 0.0001f, c1 = 1.f - 2.f * 0.0001f;
    const float inv_t = __fdividef(1.f, t);

    // each 8-lane group handles edges (e0, e0+1); warp covers 8 edges/iter
    for (int e0 = warpGlobal * 8 + sub * 2; e0 < N_EDGES; e0 += nWarps * 8) {
        const int e1 = e0 + 1;   // N_EDGES even, e0 even -> e1 < N_EDGES
        int c0, r0, c1i, r1i;
        if (is64) {
            c0 = (int)e64[e0];  r0 = (int)e64[N_EDGES + e0];
            c1i = (int)e64[e1]; r1i = (int)e64[N_EDGES + e1];
        } else {
            c0 = e32[e0];  r0 = e32[N_EDGES + e0];
            c1i = e32[e1]; r1i = e32[N_EDGES + e1];
        }

        // batch all 8 gathers before any use
        const float* Pc0 = &g_P[(size_t)c0 * NH + j8 * 8];
        const float* Pr0 = &g_P[(size_t)r0 * NH + 64 + j8 * 8];
        const float* Pc1 = &g_P[(size_t)c1i * NH + j8 * 8];
        const float* Pr1 = &g_P[(size_t)r1i * NH + 64 + j8 * 8];
        float4 a0 = *reinterpret_cast<const float4*>(Pc0);
        float4 a1 = *reinterpret_cast<const float4*>(Pc0 + 4);
        float4 b0 = *reinterpret_cast<const float4*>(Pr0);
        float4 b1 = *reinterpret_cast<const float4*>(Pr0 + 4);
        float4 a2 = *reinterpret_cast<const float4*>(Pc1);
        float4 a3 = *reinterpret_cast<const float4*>(Pc1 + 4);
        float4 b2v4 = *reinterpret_cast<const float4*>(Pr1);
        float4 b3 = *reinterpret_cast<const float4*>(Pr1 + 4);

        float p0;
        p0  = fmaxf(a0.x + b0.x + cv0.x, 0.f) * w20.x;
        p0  = fmaf(fmaxf(a0.y + b0.y + cv0.y, 0.f), w20.y, p0);
        p0  = fmaf(fmaxf(a0.z + b0.z + cv0.z, 0.f), w20.z, p0);
        p0  = fmaf(fmaxf(a0.w + b0.w + cv0.w, 0.f), w20.w, p0);
        p0  = fmaf(fmaxf(a1.x + b1.x + cv1.x, 0.f), w21.x, p0);
        p0  = fmaf(fmaxf(a1.y + b1.y + cv1.y, 0.f), w21.y, p0);
        p0  = fmaf(fmaxf(a1.z + b1.z + cv1.z, 0.f), w21.z, p0);
        p0  = fmaf(fmaxf(a1.w + b1.w + cv1.w, 0.f), w21.w, p0);

        float p1;
        p1  = fmaxf(a2.x + b2v4.x + cv0.x, 0.f) * w20.x;
        p1  = fmaf(fmaxf(a2.y + b2v4.y + cv0.y, 0.f), w20.y, p1);
        p1  = fmaf(fmaxf(a2.z + b2v4.z + cv0.z, 0.f), w20.z, p1);
        p1  = fmaf(fmaxf(a2.w + b2v4.w + cv0.w, 0.f), w20.w, p1);
        p1  = fmaf(fmaxf(a3.x + b3.x + cv1.x, 0.f), w21.x, p1);
        p1  = fmaf(fmaxf(a3.y + b3.y + cv1.y, 0.f), w21.y, p1);
        p1  = fmaf(fmaxf(a3.z + b3.z + cv1.z, 0.f), w21.z, p1);
        p1  = fmaf(fmaxf(a3.w + b3.w + cv1.w, 0.f), w21.w, p1);

        #pragma unroll
        for (int o = 4; o > 0; o >>= 1) {
            p0 += __shfl_xor_sync(0xffffffffu, p0, o);
            p1 += __shfl_xor_sync(0xffffffffu, p1, o);
        }

        if (j8 == 0) {
            float ev0 = fmaf(eps[e0], c1, bias);
            float ev1 = fmaf(eps[e1], c1, bias);
            float w0 = p0 + bb, w1 = p1 + bb;
            float o0, o1;
            if (t == 1.0f) {
                float s0 = __expf(-w0), s1 = __expf(-w1);
                o0 = __fdividef(ev0, fmaf(s0, 1.f - ev0, ev0));
                o1 = __fdividef(ev1, fmaf(s1, 1.f - ev1, ev1));
            } else {
                float g0 = (__logf(ev0) - __logf(1.f - ev0) + w0) * inv_t;
                float g1 = (__logf(ev1) - __logf(1.f - ev1) + w1) * inv_t;
                o0 = __fdividef(1.f, 1.f + __expf(-g0));
                o1 = __fdividef(1.f, 1.f + __expf(-g1));
            }
            out[e0] = o0;
            out[e1] = o1;
        }
    }
}

// ---------------------------------------------------------------------------
// Inputs: 0:x 1:embed 2:edge_index 3:node_id 4:tmp 5:eps 6:W1 7:b1 8:W2 9:b2
// ---------------------------------------------------------------------------
extern "C" void kernel_launch(void* const* d_in, const int* in_sizes, int n_in,
                              void* d_out, int out_size) {
    const float* embed = (const float*)d_in[1];
    const void*  ei    = d_in[2];
    const int*   nid   = (const int*)d_in[3];
    const float* tmp   = (const float*)d_in[4];
    const float* eps   = (const float*)d_in[5];
    const float* W1    = (const float*)d_in[6];
    const float* b1    = (const float*)d_in[7];
    const float* W2    = (const float*)d_in[8];
    const float* b2    = (const float*)d_in[9];
    float* out = (float*)d_out;

    static int attr_done = 0;
    if (!attr_done) {
        cudaFuncSetAttribute(gemm_kernel, cudaFuncAttributeMaxDynamicSharedMemorySize, SMEM_TOTAL);
        attr_done = 1;
    }

    prep_kernel<<<41, 256>>>(embed, W1, b1, nid, (const int*)ei);
    gemm_kernel<<<NTILES, 256, SMEM_TOTAL>>>(embed);
    edge_kernel<<<2368, 256>>>(ei, W2, eps, tmp, b2, out);
}